// round 1
// baseline (speedup 1.0000x reference)
#include <cuda_runtime.h>

#define N_NODES 21
#define N_EDGES 23
#define D1 64
#define D2 128
#define G_TOTAL 32768
#define WARPS_PER_BLOCK 8
#define GB 4  // graphs per warp (register-blocked in the v@W2 matvec)

// Edge list (src, tgt): message flows src -> tgt, i.e. A[tgt][src] = 1
__device__ __constant__ signed char c_esrc[N_EDGES] =
    {0,1,2,3, 0,5,6,7, 0,9,10,11, 0,13,14,15, 0,17,18,19, 5,9,13};
__device__ __constant__ signed char c_etgt[N_EDGES] =
    {1,2,3,4, 5,6,7,8, 9,10,11,12, 13,14,15,16, 17,18,19,20, 9,13,17};

// dis[i] = 1/sqrt(in_degree + self loop)
// deg: node0=1; nodes 9,13,17 = 3; all others = 2
#define R2 0.70710678118654752f
#define R3 0.57735026918962576f
__device__ __constant__ float c_dis[N_NODES] = {
    1.0f, R2, R2, R2, R2,
    R2, R2, R2, R2,
    R3, R2, R2, R2,
    R3, R2, R2, R2,
    R3, R2, R2, R2
};

__global__ void __launch_bounds__(256)
hand_gnn_kernel(const float* __restrict__ x,      // [G, 21, 2]
                const float* __restrict__ W1,     // [2, 64]
                const float* __restrict__ b1,     // [64]
                const float* __restrict__ W2,     // [64, 128]
                const float* __restrict__ b2,     // [128]
                float* __restrict__ out)          // [G, 128]
{
    __shared__ float sA[N_NODES * N_NODES];   // 441 : normalized adjacency (row t, col s)
    __shared__ float sC[N_NODES];             // c_s = (1/21) * colsum_t(A)
    __shared__ float sW1[2 * D1];
    __shared__ float sB1[D1];
    __shared__ float sB2[D2];
    __shared__ float sW2[D1 * D2];            // 8192 floats = 32 KB
    __shared__ float2 sx[WARPS_PER_BLOCK][N_NODES];
    __shared__ float2 sy[WARPS_PER_BLOCK][N_NODES];
    __shared__ float  sv[WARPS_PER_BLOCK][GB][D1];

    const int tid = threadIdx.x;

    // ---- build normalized adjacency + load weights into shared ----
    for (int i = tid; i < N_NODES * N_NODES; i += blockDim.x) sA[i] = 0.0f;
    for (int i = tid; i < 2 * D1; i += blockDim.x) sW1[i] = W1[i];
    for (int i = tid; i < D1; i += blockDim.x) sB1[i] = b1[i];
    for (int i = tid; i < D2; i += blockDim.x) sB2[i] = b2[i];
    for (int i = tid; i < D1 * D2; i += blockDim.x) sW2[i] = W2[i];
    __syncthreads();
    if (tid < N_NODES) {
        sA[tid * N_NODES + tid] = c_dis[tid] * c_dis[tid];   // self loop
    } else if (tid < N_NODES + N_EDGES) {
        int e = tid - N_NODES;
        int s = c_esrc[e], t = c_etgt[e];
        sA[t * N_NODES + s] = c_dis[t] * c_dis[s];
    }
    __syncthreads();
    if (tid < N_NODES) {
        float acc = 0.0f;
        #pragma unroll
        for (int t = 0; t < N_NODES; t++) acc += sA[t * N_NODES + tid];
        sC[tid] = acc * (1.0f / 21.0f);
    }
    __syncthreads();

    const int w    = tid >> 5;
    const int lane = tid & 31;
    const int g0   = (blockIdx.x * WARPS_PER_BLOCK + w) * GB;
    if (g0 >= G_TOTAL) return;   // no __syncthreads below this point

    // Per-lane loop-invariant weights for layer-1 feature channels f=lane, f=lane+32
    const float w1a0 = sW1[lane],      w1a1 = sW1[D1 + lane],      b1a = sB1[lane];
    const float w1b0 = sW1[lane + 32], w1b1 = sW1[D1 + lane + 32], b1b = sB1[lane + 32];

    const float2* xg = reinterpret_cast<const float2*>(x) + (size_t)g0 * N_NODES;

    // ---- per graph: y = A@x (21x2), then v_f = sum_t c_t * relu(y@W1 + b1) ----
    #pragma unroll
    for (int j = 0; j < GB; j++) {
        if (lane < N_NODES) sx[w][lane] = xg[j * N_NODES + lane];
        __syncwarp();
        if (lane < N_NODES) {
            float y0 = 0.0f, y1 = 0.0f;
            #pragma unroll
            for (int s = 0; s < N_NODES; s++) {
                float a = sA[lane * N_NODES + s];   // stride-21 across lanes: conflict-free
                float2 xs = sx[w][s];               // broadcast
                y0 = fmaf(a, xs.x, y0);
                y1 = fmaf(a, xs.y, y1);
            }
            sy[w][lane] = make_float2(y0, y1);
        }
        __syncwarp();
        float va = 0.0f, vb = 0.0f;
        #pragma unroll
        for (int t = 0; t < N_NODES; t++) {
            float2 yt = sy[w][t];                   // broadcast
            float ct  = sC[t];                      // broadcast
            float ha = fmaf(yt.x, w1a0, fmaf(yt.y, w1a1, b1a));
            float hb = fmaf(yt.x, w1b0, fmaf(yt.y, w1b1, b1b));
            va = fmaf(ct, fmaxf(ha, 0.0f), va);
            vb = fmaf(ct, fmaxf(hb, 0.0f), vb);
        }
        sv[w][j][lane]      = va;
        sv[w][j][lane + 32] = vb;
        __syncwarp();
    }

    // ---- out = v @ W2 + b2, register-blocked over GB graphs ----
    float acc[GB][4];
    #pragma unroll
    for (int j = 0; j < GB; j++) {
        acc[j][0] = sB2[lane];
        acc[j][1] = sB2[lane + 32];
        acc[j][2] = sB2[lane + 64];
        acc[j][3] = sB2[lane + 96];
    }
    #pragma unroll 8
    for (int f = 0; f < D1; f++) {
        const float* w2f = sW2 + f * D2;
        float q0 = w2f[lane];
        float q1 = w2f[lane + 32];
        float q2 = w2f[lane + 64];
        float q3 = w2f[lane + 96];
        #pragma unroll
        for (int j = 0; j < GB; j++) {
            float vf = sv[w][j][f];                 // broadcast
            acc[j][0] = fmaf(vf, q0, acc[j][0]);
            acc[j][1] = fmaf(vf, q1, acc[j][1]);
            acc[j][2] = fmaf(vf, q2, acc[j][2]);
            acc[j][3] = fmaf(vf, q3, acc[j][3]);
        }
    }
    #pragma unroll
    for (int j = 0; j < GB; j++) {
        float* og = out + (size_t)(g0 + j) * D2;
        og[lane]      = acc[j][0];
        og[lane + 32] = acc[j][1];
        og[lane + 64] = acc[j][2];
        og[lane + 96] = acc[j][3];
    }
}

extern "C" void kernel_launch(void* const* d_in, const int* in_sizes, int n_in,
                              void* d_out, int out_size) {
    const float* x  = (const float*)d_in[0];   // [64,512,21,2]
    const float* W1 = (const float*)d_in[1];   // [2,64]
    const float* b1 = (const float*)d_in[2];   // [64]
    const float* W2 = (const float*)d_in[3];   // [64,128]
    const float* b2 = (const float*)d_in[4];   // [128]
    float* out = (float*)d_out;                // [64,512,128]

    const int blocks = G_TOTAL / (WARPS_PER_BLOCK * GB);  // 1024
    hand_gnn_kernel<<<blocks, 256>>>(x, W1, b1, W2, b2, out);
}

// round 2
// speedup vs baseline: 1.0423x; 1.0423x over previous
#include <cuda_runtime.h>

#define N_NODES 21
#define N_EDGES 23
#define D1 64
#define D2 128
#define G_TOTAL 32768
#define WARPS_PER_BLOCK 8
#define GB 4

typedef unsigned long long ull;
struct __align__(16) ull2 { ull x, y; };

__device__ __forceinline__ ull ffma2(ull a, ull b, ull c) {
    ull d;
    asm("fma.rn.f32x2 %0, %1, %2, %3;" : "=l"(d) : "l"(a), "l"(b), "l"(c));
    return d;
}
__device__ __forceinline__ ull pack2(float lo, float hi) {
    ull d;
    asm("mov.b64 %0, {%1, %2};" : "=l"(d) : "f"(lo), "f"(hi));
    return d;
}
__device__ __forceinline__ void unpack2(ull v, float& lo, float& hi) {
    asm("mov.b64 {%0, %1}, %2;" : "=f"(lo), "=f"(hi) : "l"(v));
}

__device__ __constant__ signed char c_esrc[N_EDGES] =
    {0,1,2,3, 0,5,6,7, 0,9,10,11, 0,13,14,15, 0,17,18,19, 5,9,13};
__device__ __constant__ signed char c_etgt[N_EDGES] =
    {1,2,3,4, 5,6,7,8, 9,10,11,12, 13,14,15,16, 17,18,19,20, 9,13,17};

#define R2 0.70710678118654752f
#define R3 0.57735026918962576f
__device__ __constant__ float c_dis[N_NODES] = {
    1.0f, R2, R2, R2, R2,
    R2, R2, R2, R2,
    R3, R2, R2, R2,
    R3, R2, R2, R2,
    R3, R2, R2, R2
};

__global__ void __launch_bounds__(256)
hand_gnn_kernel(const float* __restrict__ x,      // [G, 21, 2]
                const float* __restrict__ W1,     // [2, 64]
                const float* __restrict__ b1,     // [64]
                const float* __restrict__ W2,     // [64, 128]
                const float* __restrict__ b2,     // [128]
                float* __restrict__ out)          // [G, 128]
{
    __shared__ __align__(16) float  sA[N_NODES * N_NODES];          // adjacency [t][s]
    __shared__ __align__(8)  float2 sC2[N_NODES];                   // (c_t/2, c_t/2)
    __shared__ __align__(16) float  sW2[D1 * D2];                   // 32 KB
    __shared__ __align__(8)  float2 sx [WARPS_PER_BLOCK][N_NODES];  // raw x per graph
    __shared__ __align__(16) float4 sy2[WARPS_PER_BLOCK][N_NODES];  // (y0,y0,y1,y1)
    __shared__ __align__(16) float  sv [WARPS_PER_BLOCK][D1][GB];   // v[f][graph]

    const int tid = threadIdx.x;

    // ---- prolog: adjacency + W2 into shared ----
    for (int i = tid; i < N_NODES * N_NODES; i += blockDim.x) sA[i] = 0.0f;
    for (int i = tid; i < D1 * D2; i += blockDim.x) sW2[i] = W2[i];
    __syncthreads();
    if (tid < N_NODES) {
        sA[tid * N_NODES + tid] = c_dis[tid] * c_dis[tid];
    } else if (tid < N_NODES + N_EDGES) {
        int e = tid - N_NODES;
        int s = c_esrc[e], t = c_etgt[e];
        sA[t * N_NODES + s] = c_dis[t] * c_dis[s];
    }
    __syncthreads();
    if (tid < N_NODES) {
        float acc = 0.0f;
        #pragma unroll
        for (int t = 0; t < N_NODES; t++) acc += sA[t * N_NODES + tid];
        float ch = acc * (1.0f / 42.0f);              // c_t / 2
        sC2[tid] = make_float2(ch, ch);
    }
    __syncthreads();

    const int w    = tid >> 5;
    const int lane = tid & 31;
    const int g0   = (blockIdx.x * WARPS_PER_BLOCK + w) * GB;

    // layer-1 weights packed per lane: channels (lane, lane+32)
    const ull W10p = pack2(W1[lane],      W1[lane + 32]);
    const ull W11p = pack2(W1[D1 + lane], W1[D1 + lane + 32]);
    const ull B1p  = pack2(b1[lane],      b1[lane + 32]);
    // b2 for the 4 output cols this lane owns
    const ull2 B2  = *reinterpret_cast<const ull2*>(b2 + 4 * lane);

    const float2* xg = reinterpret_cast<const float2*>(x) + (size_t)g0 * N_NODES;
    const ull ABSMASK = 0x7FFFFFFF7FFFFFFFull;

    // ---- layer 1, per graph ----
    #pragma unroll
    for (int j = 0; j < GB; j++) {
        if (lane < N_NODES) sx[w][lane] = xg[j * N_NODES + lane];
        __syncwarp();
        if (lane < N_NODES) {
            // y = A @ x  (packed over the 2 input channels)
            ull y2 = 0;
            #pragma unroll
            for (int s = 0; s < N_NODES; s++) {
                float a = sA[lane * N_NODES + s];
                ull xs = *reinterpret_cast<const ull*>(&sx[w][s]);
                y2 = ffma2(pack2(a, a), xs, y2);
            }
            float y0, y1; unpack2(y2, y0, y1);
            sy2[w][lane] = make_float4(y0, y0, y1, y1);
        }
        __syncwarp();
        // v_f = sum_t (c_t/2)*h + (c_t/2)*|h|,  h = y@W1 + b1   (== c_t*relu(h))
        ull v2 = 0;
        #pragma unroll
        for (int t = 0; t < N_NODES; t++) {
            ull2 yd = *reinterpret_cast<const ull2*>(&sy2[w][t]);   // (y0,y0),(y1,y1)
            ull c2  = *reinterpret_cast<const ull*>(&sC2[t]);
            ull h2  = ffma2(yd.x, W10p, ffma2(yd.y, W11p, B1p));
            v2 = ffma2(c2, h2, ffma2(c2, h2 & ABSMASK, v2));
        }
        float va, vb; unpack2(v2, va, vb);
        sv[w][lane][j]      = va;      // f = lane
        sv[w][lane + 32][j] = vb;      // f = lane + 32
        __syncwarp();
    }

    // ---- epilogue: out = v @ W2 + b2, lane owns cols [4*lane, 4*lane+4) ----
    ull a0[GB], a1[GB];
    #pragma unroll
    for (int j = 0; j < GB; j++) { a0[j] = B2.x; a1[j] = B2.y; }

    #pragma unroll 8
    for (int f = 0; f < D1; f++) {
        ull2 q = *reinterpret_cast<const ull2*>(sW2 + f * D2 + 4 * lane); // LDS.128
        float4 vv = *reinterpret_cast<const float4*>(&sv[w][f][0]);       // broadcast
        ull v0 = pack2(vv.x, vv.x);
        ull v1 = pack2(vv.y, vv.y);
        ull v2_ = pack2(vv.z, vv.z);
        ull v3 = pack2(vv.w, vv.w);
        a0[0] = ffma2(v0, q.x, a0[0]);  a1[0] = ffma2(v0, q.y, a1[0]);
        a0[1] = ffma2(v1, q.x, a0[1]);  a1[1] = ffma2(v1, q.y, a1[1]);
        a0[2] = ffma2(v2_, q.x, a0[2]); a1[2] = ffma2(v2_, q.y, a1[2]);
        a0[3] = ffma2(v3, q.x, a0[3]);  a1[3] = ffma2(v3, q.y, a1[3]);
    }

    #pragma unroll
    for (int j = 0; j < GB; j++) {
        ull2 r; r.x = a0[j]; r.y = a1[j];
        *reinterpret_cast<ull2*>(out + (size_t)(g0 + j) * D2 + 4 * lane) = r; // STG.128
    }
}

extern "C" void kernel_launch(void* const* d_in, const int* in_sizes, int n_in,
                              void* d_out, int out_size) {
    const float* x  = (const float*)d_in[0];
    const float* W1 = (const float*)d_in[1];
    const float* b1 = (const float*)d_in[2];
    const float* W2 = (const float*)d_in[3];
    const float* b2 = (const float*)d_in[4];
    float* out = (float*)d_out;

    const int blocks = G_TOTAL / (WARPS_PER_BLOCK * GB);  // 1024
    hand_gnn_kernel<<<blocks, 256>>>(x, W1, b1, W2, b2, out);
}